// round 12
// baseline (speedup 1.0000x reference)
#include <cuda_runtime.h>
#include <cuda_fp16.h>
#include <cstdint>

namespace {
constexpr int S_    = 2048;
constexpr int H_    = 32;
constexpr int G_    = 4;
constexpr int D_    = 128;
constexpr int QSTR  = 4096;   // H*D floats per token (q, out)
constexpr int KSTR  = 1024;   // HKV*D per token (k, v)
constexpr int BM    = 64;     // q rows per CTA
constexpr int BN    = 64;     // kv rows per tile
constexpr int NT    = 128;    // threads (4 warps)
constexpr int STRIDE = 136;   // smem row stride in halves (128 + 8 pad)
constexpr int KV_ELE = BN * STRIDE;           // 8704 halves = 17408 B (= sQ size)
// layout (halves): [sQ(=V slot 2) | K0 K1 K2 | V0 V1]
constexpr int SMEM_BYTES = 6 * KV_ELE * 2;    // 104448 B -> 2 CTAs/SM
}

// fp16 copies of K/V (scratch)
__device__ __align__(16) half g_kh[2 * S_ * KSTR];
__device__ __align__(16) half g_vh[2 * S_ * KSTR];

__device__ __forceinline__ uint32_t smem_u32(const void* p) {
    return (uint32_t)__cvta_generic_to_shared(p);
}
__device__ __forceinline__ void cp_async16(uint32_t dst, const void* src) {
    asm volatile("cp.async.cg.shared.global [%0], [%1], 16;\n" :: "r"(dst), "l"(src));
}
__device__ __forceinline__ void ldm_x4(uint32_t& r0, uint32_t& r1, uint32_t& r2, uint32_t& r3, uint32_t a) {
    asm volatile("ldmatrix.sync.aligned.m8n8.x4.shared.b16 {%0,%1,%2,%3}, [%4];\n"
        : "=r"(r0), "=r"(r1), "=r"(r2), "=r"(r3) : "r"(a));
}
__device__ __forceinline__ void ldm_x4_t(uint32_t& r0, uint32_t& r1, uint32_t& r2, uint32_t& r3, uint32_t a) {
    asm volatile("ldmatrix.sync.aligned.m8n8.x4.trans.shared.b16 {%0,%1,%2,%3}, [%4];\n"
        : "=r"(r0), "=r"(r1), "=r"(r2), "=r"(r3) : "r"(a));
}
__device__ __forceinline__ void mma16816(float* c, const uint32_t* a, uint32_t b0, uint32_t b1) {
    asm volatile("mma.sync.aligned.m16n8k16.row.col.f32.f16.f16.f32 "
        "{%0,%1,%2,%3}, {%4,%5,%6,%7}, {%8,%9}, {%0,%1,%2,%3};\n"
        : "+f"(c[0]), "+f"(c[1]), "+f"(c[2]), "+f"(c[3])
        : "r"(a[0]), "r"(a[1]), "r"(a[2]), "r"(a[3]), "r"(b0), "r"(b1));
}
__device__ __forceinline__ uint32_t packh2(float x, float y) {
    half2 h = __floats2half2_rn(x, y);
    return *reinterpret_cast<uint32_t*>(&h);
}
// p_half2 = ex2.approx.f16x2( half2(lo, hi) )
__device__ __forceinline__ uint32_t exp2_h2(float lo, float hi) {
    uint32_t h, p;
    asm volatile("cvt.rn.f16x2.f32 %0, %1, %2;\n" : "=r"(h) : "f"(hi), "f"(lo));
    asm volatile("ex2.approx.f16x2 %0, %1;\n" : "=r"(p) : "r"(h));
    return p;
}

// ---- K/V fp32 -> fp16 convert pass ----
__global__ void cvt_kernel(const float* __restrict__ k, const float* __restrict__ v) {
    const size_t n4 = (size_t)2 * S_ * KSTR / 4;
    for (size_t i = (size_t)blockIdx.x * blockDim.x + threadIdx.x;
         i < 2 * n4; i += (size_t)gridDim.x * blockDim.x) {
        bool isK = i < n4;
        size_t ii = isK ? i : i - n4;
        float4 f = isK ? ((const float4*)k)[ii] : ((const float4*)v)[ii];
        uint2 h;
        h.x = packh2(f.x, f.y);
        h.y = packh2(f.z, f.w);
        ((uint2*)(isK ? g_kh : g_vh))[ii] = h;
    }
}

__global__ __launch_bounds__(NT, 2)
void fa2_kernel(const float* __restrict__ q, float* __restrict__ o)
{
    extern __shared__ __align__(16) half smem[];
    half* sQ    = smem;                     // doubles as V ring slot 2 after prologue
    half* sKbuf = smem + KV_ELE;            // K ring: 3 slots
    half* sV01  = smem + 4 * KV_ELE;        // V ring slots 0,1

    const int tid  = threadIdx.x;
    const int warp = tid >> 5;
    const int lane = tid & 31;
    const int qt   = (int)gridDim.x - 1 - (int)blockIdx.x;  // heavy tiles first
    const int hq   = blockIdx.y;
    const int b    = blockIdx.z;
    const int hkv  = hq / G_;
    const int qbase = qt * BM;
    const int ntile = (qbase + BM) / BN;   // = qt + 1 >= 1

    const size_t tok0 = (size_t)b * S_ + qbase;
    const half* kg = g_kh + ((size_t)b * S_) * KSTR + (size_t)hkv * D_;
    const half* vg = g_vh + ((size_t)b * S_) * KSTR + (size_t)hkv * D_;

    auto vbuf = [&](int t) -> half* {
        int s = t % 3;
        return (s < 2) ? (sV01 + s * KV_ELE) : sQ;
    };
    auto load_kv = [&](int t) {
        const half* kt = kg + (size_t)(t * BN) * KSTR;
        const half* vt = vg + (size_t)(t * BN) * KSTR;
        half* dK = sKbuf + (t % 3) * KV_ELE;
        half* dV = vbuf(t);
        #pragma unroll
        for (int i = tid; i < BN * 16; i += NT) {
            int r = i >> 4, c = (i & 15) * 8;
            cp_async16(smem_u32(dK + r * STRIDE + c), kt + (size_t)r * KSTR + c);
            cp_async16(smem_u32(dV + r * STRIDE + c), vt + (size_t)r * KSTR + c);
        }
    };
    // prologue: tiles 0 and 1 (V slots 0,1 — never alias sQ)
    load_kv(0);
    asm volatile("cp.async.commit_group;\n");
    if (1 < ntile) load_kv(1);
    asm volatile("cp.async.commit_group;\n");

    // ---- stage Q (fp32 -> fp16) while cp.async is in flight ----
    const float* qg = q + tok0 * QSTR + (size_t)hq * D_;
    for (int i = tid; i < BM * 32; i += NT) {
        int r = i >> 5, c = (i & 31) * 4;
        float4 f = *(const float4*)(qg + (size_t)r * QSTR + c);
        half2* d = (half2*)(sQ + r * STRIDE + c);
        d[0] = __floats2half2_rn(f.x, f.y);
        d[1] = __floats2half2_rn(f.z, f.w);
    }
    __syncthreads();

    // ---- Q fragments (persistent); warp owns rows warp*16 .. +15 ----
    uint32_t qf[8][4];
    {
        int j = lane >> 3, m = lane & 7;
        int row = warp * 16 + ((j & 1) ? 8 : 0) + m;
        int col = (j >= 2) ? 8 : 0;
        #pragma unroll
        for (int kc = 0; kc < 8; kc++) {
            uint32_t a = smem_u32(sQ + row * STRIDE + kc * 16 + col);
            ldm_x4(qf[kc][0], qf[kc][1], qf[kc][2], qf[kc][3], a);
        }
    }
    // sQ now dead as Q storage; first reuse as V slot is tile 2 (issued after
    // the first in-loop __syncthreads, so all warps are past the reads above).

    constexpr float SL = 0.08838834764831845f * 1.4426950408889634f;  // SCALE*log2(e)
    float ot[16][4];
    #pragma unroll
    for (int t = 0; t < 16; t++)
        #pragma unroll
        for (int i = 0; i < 4; i++) ot[t][i] = 0.f;
    float lacc[4] = {0.f, 0.f, 0.f, 0.f};  // l via ones-column mma
    float m0 = -1e30f, m1 = -1e30f;

    const uint32_t onesB = (lane < 4) ? 0x3C003C00u : 0u;

    const int r0g = qbase + warp * 16 + (lane >> 2);
    const int r1g = r0g + 8;
    const int wrow = qbase + warp * 16;

    for (int j = 0; j < ntile; j++) {
        // single barrier per tile: KV group j complete; every warp past iter j-1,
        // so ring slot (j+2)%3 (== (j-1)%3) is safe to overwrite.
        asm volatile("cp.async.wait_group 1;\n");
        __syncthreads();
        if (j + 2 < ntile) load_kv(j + 2);
        asm volatile("cp.async.commit_group;\n");

        const half* sK = sKbuf + (j % 3) * KV_ELE;
        const half* sV = vbuf(j);

        bool skip = (wrow + 15) < j * BN;
        if (!skip) {
            // ---- S = Q K^T (raw scores) ----
            float sc[8][4];
            #pragma unroll
            for (int t = 0; t < 8; t++)
                #pragma unroll
                for (int i = 0; i < 4; i++) sc[t][i] = 0.f;
            {
                int jj = lane >> 3, mm = lane & 7;
                int rn = ((jj >= 2) ? 8 : 0) + mm;
                int ck = (jj & 1) ? 8 : 0;
                #pragma unroll
                for (int kc = 0; kc < 8; kc++) {
                    #pragma unroll
                    for (int np = 0; np < 4; np++) {
                        uint32_t a = smem_u32(sK + (np * 16 + rn) * STRIDE + kc * 16 + ck);
                        uint32_t b0, b1, b2, b3;
                        ldm_x4(b0, b1, b2, b3, a);
                        mma16816(sc[2 * np],     qf[kc], b0, b1);
                        mma16816(sc[2 * np + 1], qf[kc], b2, b3);
                    }
                }
            }

            // ---- causal mask on raw scores (straddle tiles only) ----
            bool needMask = (j * BN + BN - 1) > wrow;
            if (needMask) {
                int c0 = j * BN + (lane & 3) * 2;
                #pragma unroll
                for (int nt = 0; nt < 8; nt++) {
                    int cc = c0 + nt * 8;
                    if (cc     > r0g) sc[nt][0] = -1e30f;
                    if (cc + 1 > r0g) sc[nt][1] = -1e30f;
                    if (cc     > r1g) sc[nt][2] = -1e30f;
                    if (cc + 1 > r1g) sc[nt][3] = -1e30f;
                }
            }

            // ---- max on RAW scores ----
            float t0 = sc[0][0], t1 = sc[0][2];
            #pragma unroll
            for (int nt = 0; nt < 8; nt++) {
                t0 = fmaxf(t0, fmaxf(sc[nt][0], sc[nt][1]));
                t1 = fmaxf(t1, fmaxf(sc[nt][2], sc[nt][3]));
            }
            t0 = fmaxf(t0, __shfl_xor_sync(0xffffffffu, t0, 1));
            t0 = fmaxf(t0, __shfl_xor_sync(0xffffffffu, t0, 2));
            t1 = fmaxf(t1, __shfl_xor_sync(0xffffffffu, t1, 1));
            t1 = fmaxf(t1, __shfl_xor_sync(0xffffffffu, t1, 2));
            float nm0 = fmaxf(m0, t0 * SL);
            float nm1 = fmaxf(m1, t1 * SL);
            float a0 = exp2f(m0 - nm0), a1 = exp2f(m1 - nm1);
            m0 = nm0; m1 = nm1;

            // ---- h = s*SL - m ----
            #pragma unroll
            for (int nt = 0; nt < 8; nt++) {
                sc[nt][0] = fmaf(sc[nt][0], SL, -m0);
                sc[nt][1] = fmaf(sc[nt][1], SL, -m0);
                sc[nt][2] = fmaf(sc[nt][2], SL, -m1);
                sc[nt][3] = fmaf(sc[nt][3], SL, -m1);
            }

            // ---- rescale O and l only when a row max moved (exact skip of x1.0) ----
            if (__any_sync(0xffffffffu, (a0 != 1.f) || (a1 != 1.f))) {
                #pragma unroll
                for (int t = 0; t < 16; t++) {
                    ot[t][0] *= a0; ot[t][1] *= a0;
                    ot[t][2] *= a1; ot[t][3] *= a1;
                }
                lacc[0] *= a0; lacc[2] *= a1;
            }

            // ---- P = ex2(h) fp16x2; PV mma + l via ones-column mma ----
            {
                int jj = lane >> 3, mm = lane & 7;
                int rk = (jj & 1) * 8 + mm;
                int cn = (jj >= 2) ? 8 : 0;
                #pragma unroll
                for (int kvc = 0; kvc < 4; kvc++) {
                    uint32_t af[4];
                    af[0] = exp2_h2(sc[2 * kvc][0],     sc[2 * kvc][1]);
                    af[1] = exp2_h2(sc[2 * kvc][2],     sc[2 * kvc][3]);
                    af[2] = exp2_h2(sc[2 * kvc + 1][0], sc[2 * kvc + 1][1]);
                    af[3] = exp2_h2(sc[2 * kvc + 1][2], sc[2 * kvc + 1][3]);
                    mma16816(lacc, af, onesB, onesB);
                    #pragma unroll
                    for (int dp = 0; dp < 8; dp++) {
                        uint32_t b0, b1, b2, b3;
                        uint32_t a = smem_u32(sV + (kvc * 16 + rk) * STRIDE + dp * 16 + cn);
                        ldm_x4_t(b0, b1, b2, b3, a);
                        mma16816(ot[2 * dp],     af, b0, b1);
                        mma16816(ot[2 * dp + 1], af, b2, b3);
                    }
                }
            }
        }
    }

    // ---- epilogue: broadcast l (col 0 lives in lane&~3), normalize, store ----
    float lr0 = __shfl_sync(0xffffffffu, lacc[0], lane & ~3);
    float lr1 = __shfl_sync(0xffffffffu, lacc[2], lane & ~3);
    float inv0 = 1.f / lr0, inv1 = 1.f / lr1;
    float* og = o + tok0 * QSTR + (size_t)hq * D_;
    int rr0 = warp * 16 + (lane >> 2);
    #pragma unroll
    for (int nt = 0; nt < 16; nt++) {
        int c = nt * 8 + (lane & 3) * 2;
        float2 w0 = make_float2(ot[nt][0] * inv0, ot[nt][1] * inv0);
        float2 w1 = make_float2(ot[nt][2] * inv1, ot[nt][3] * inv1);
        *(float2*)(og + (size_t)rr0 * QSTR + c)       = w0;
        *(float2*)(og + (size_t)(rr0 + 8) * QSTR + c) = w1;
    }
}

extern "C" void kernel_launch(void* const* d_in, const int* in_sizes, int n_in,
                              void* d_out, int out_size)
{
    const float* q = (const float*)d_in[0];
    const float* k = (const float*)d_in[1];
    const float* v = (const float*)d_in[2];
    float* o = (float*)d_out;

    cvt_kernel<<<2048, 256>>>(k, v);

    cudaFuncSetAttribute(fa2_kernel, cudaFuncAttributeMaxDynamicSharedMemorySize, SMEM_BYTES);
    dim3 grid(S_ / BM, H_, 2);   // 32 x 32 x 2 = 2048 CTAs
    fa2_kernel<<<grid, NT, SMEM_BYTES>>>(q, o);
}

// round 14
// speedup vs baseline: 1.4561x; 1.4561x over previous
#include <cuda_runtime.h>
#include <cuda_fp16.h>
#include <cstdint>

namespace {
constexpr int S_    = 2048;
constexpr int H_    = 32;
constexpr int G_    = 4;
constexpr int D_    = 128;
constexpr int QSTR  = 4096;   // H*D floats per token (q, out)
constexpr int KSTR  = 1024;   // HKV*D per token (k, v)
constexpr int BM    = 64;     // q rows per CTA
constexpr int BN    = 64;     // kv rows per tile
constexpr int NT    = 128;    // threads (4 warps)
constexpr int STRIDE = 136;   // smem row stride in halves (128 + 8 pad)
constexpr int KV_ELE = BN * STRIDE;
// sQ (64 rows) + 2*sK + 2*sV
constexpr int SMEM_BYTES = (BM * STRIDE + 4 * KV_ELE) * 2;   // 87,040 B -> 2 CTAs/SM
}

// fp16 copies of K/V (scratch)
__device__ __align__(16) half g_kh[2 * S_ * KSTR];
__device__ __align__(16) half g_vh[2 * S_ * KSTR];

__device__ __forceinline__ uint32_t smem_u32(const void* p) {
    return (uint32_t)__cvta_generic_to_shared(p);
}
__device__ __forceinline__ void cp_async16(uint32_t dst, const void* src) {
    asm volatile("cp.async.cg.shared.global [%0], [%1], 16;\n" :: "r"(dst), "l"(src));
}
__device__ __forceinline__ void ldm_x4(uint32_t& r0, uint32_t& r1, uint32_t& r2, uint32_t& r3, uint32_t a) {
    asm volatile("ldmatrix.sync.aligned.m8n8.x4.shared.b16 {%0,%1,%2,%3}, [%4];\n"
        : "=r"(r0), "=r"(r1), "=r"(r2), "=r"(r3) : "r"(a));
}
__device__ __forceinline__ void ldm_x4_t(uint32_t& r0, uint32_t& r1, uint32_t& r2, uint32_t& r3, uint32_t a) {
    asm volatile("ldmatrix.sync.aligned.m8n8.x4.trans.shared.b16 {%0,%1,%2,%3}, [%4];\n"
        : "=r"(r0), "=r"(r1), "=r"(r2), "=r"(r3) : "r"(a));
}
__device__ __forceinline__ void mma16816(float* c, const uint32_t* a, uint32_t b0, uint32_t b1) {
    asm volatile("mma.sync.aligned.m16n8k16.row.col.f32.f16.f16.f32 "
        "{%0,%1,%2,%3}, {%4,%5,%6,%7}, {%8,%9}, {%0,%1,%2,%3};\n"
        : "+f"(c[0]), "+f"(c[1]), "+f"(c[2]), "+f"(c[3])
        : "r"(a[0]), "r"(a[1]), "r"(a[2]), "r"(a[3]), "r"(b0), "r"(b1));
}
__device__ __forceinline__ uint32_t packh2(float x, float y) {
    half2 h = __floats2half2_rn(x, y);
    return *reinterpret_cast<uint32_t*>(&h);
}
// p_half2 = ex2.approx.f16x2( half2(lo, hi) )
__device__ __forceinline__ uint32_t exp2_h2(float lo, float hi) {
    uint32_t h, p;
    asm volatile("cvt.rn.f16x2.f32 %0, %1, %2;\n" : "=r"(h) : "f"(hi), "f"(lo));
    asm volatile("ex2.approx.f16x2 %0, %1;\n" : "=r"(p) : "r"(h));
    return p;
}

// ---- K/V fp32 -> fp16 convert pass ----
__global__ void cvt_kernel(const float* __restrict__ k, const float* __restrict__ v) {
    const size_t n4 = (size_t)2 * S_ * KSTR / 4;
    for (size_t i = (size_t)blockIdx.x * blockDim.x + threadIdx.x;
         i < 2 * n4; i += (size_t)gridDim.x * blockDim.x) {
        bool isK = i < n4;
        size_t ii = isK ? i : i - n4;
        float4 f = isK ? ((const float4*)k)[ii] : ((const float4*)v)[ii];
        uint2 h;
        h.x = packh2(f.x, f.y);
        h.y = packh2(f.z, f.w);
        ((uint2*)(isK ? g_kh : g_vh))[ii] = h;
    }
}

__global__ __launch_bounds__(NT, 2)
void fa2_kernel(const float* __restrict__ q, float* __restrict__ o)
{
    extern __shared__ __align__(16) half smem[];
    half* sQ    = smem;                     // BM * STRIDE
    half* sKbuf = smem + BM * STRIDE;       // 2 bufs
    half* sVbuf = sKbuf + 2 * KV_ELE;       // 2 bufs

    const int tid  = threadIdx.x;
    const int warp = tid >> 5;
    const int lane = tid & 31;
    const int qt   = (int)gridDim.x - 1 - (int)blockIdx.x;  // heavy tiles first
    const int hq   = blockIdx.y;
    const int b    = blockIdx.z;
    const int hkv  = hq / G_;
    const int qbase = qt * BM;
    const int ntile = (qbase + BM) / BN;   // = qt + 1 >= 1

    const size_t tok0 = (size_t)b * S_ + qbase;
    const half* kg = g_kh + ((size_t)b * S_) * KSTR + (size_t)hkv * D_;
    const half* vg = g_vh + ((size_t)b * S_) * KSTR + (size_t)hkv * D_;

    auto load_kv = [&](int j, int buf) {
        const half* kt = kg + (size_t)(j * BN) * KSTR;
        const half* vt = vg + (size_t)(j * BN) * KSTR;
        half* dK = sKbuf + buf * KV_ELE;
        half* dV = sVbuf + buf * KV_ELE;
        #pragma unroll
        for (int i = tid; i < BN * 16; i += NT) {
            int r = i >> 4, c = (i & 15) * 8;
            cp_async16(smem_u32(dK + r * STRIDE + c), kt + (size_t)r * KSTR + c);
            cp_async16(smem_u32(dV + r * STRIDE + c), vt + (size_t)r * KSTR + c);
        }
    };
    load_kv(0, 0);
    asm volatile("cp.async.commit_group;\n");
    if (1 < ntile) load_kv(1, 1);
    asm volatile("cp.async.commit_group;\n");

    // ---- stage Q (fp32 -> fp16) while cp.async is in flight ----
    const float* qg = q + tok0 * QSTR + (size_t)hq * D_;
    for (int i = tid; i < BM * 32; i += NT) {
        int r = i >> 5, c = (i & 31) * 4;
        float4 f = *(const float4*)(qg + (size_t)r * QSTR + c);
        half2* d = (half2*)(sQ + r * STRIDE + c);
        d[0] = __floats2half2_rn(f.x, f.y);
        d[1] = __floats2half2_rn(f.z, f.w);
    }
    __syncthreads();

    // ---- Q fragments (persistent); warp owns rows warp*16 .. +15 ----
    uint32_t qf[8][4];
    {
        int j = lane >> 3, m = lane & 7;
        int row = warp * 16 + ((j & 1) ? 8 : 0) + m;
        int col = (j >= 2) ? 8 : 0;
        #pragma unroll
        for (int kc = 0; kc < 8; kc++) {
            uint32_t a = smem_u32(sQ + row * STRIDE + kc * 16 + col);
            ldm_x4(qf[kc][0], qf[kc][1], qf[kc][2], qf[kc][3], a);
        }
    }

    constexpr float SL = 0.08838834764831845f * 1.4426950408889634f;  // SCALE*log2(e)
    float ot[16][4];
    #pragma unroll
    for (int t = 0; t < 16; t++)
        #pragma unroll
        for (int i = 0; i < 4; i++) ot[t][i] = 0.f;
    float lacc[4] = {0.f, 0.f, 0.f, 0.f};  // l via ones-column mma
    float m0 = -1e30f, m1 = -1e30f;

    const uint32_t onesB = (lane < 4) ? 0x3C003C00u : 0u;

    const int r0g = qbase + warp * 16 + (lane >> 2);
    const int r1g = r0g + 8;
    const int wrow = qbase + warp * 16;

    for (int j = 0; j < ntile; j++) {
        asm volatile("cp.async.wait_group 1;\n");
        __syncthreads();

        const half* sK = sKbuf + (j & 1) * KV_ELE;
        const half* sV = sVbuf + (j & 1) * KV_ELE;

        {
            // ---- S = Q K^T (raw scores) ----
            float sc[8][4];
            #pragma unroll
            for (int t = 0; t < 8; t++)
                #pragma unroll
                for (int i = 0; i < 4; i++) sc[t][i] = 0.f;
            {
                int jj = lane >> 3, mm = lane & 7;
                int rn = ((jj >= 2) ? 8 : 0) + mm;
                int ck = (jj & 1) ? 8 : 0;
                #pragma unroll
                for (int kc = 0; kc < 8; kc++) {
                    #pragma unroll
                    for (int np = 0; np < 4; np++) {
                        uint32_t a = smem_u32(sK + (np * 16 + rn) * STRIDE + kc * 16 + ck);
                        uint32_t b0, b1, b2, b3;
                        ldm_x4(b0, b1, b2, b3, a);
                        mma16816(sc[2 * np],     qf[kc], b0, b1);
                        mma16816(sc[2 * np + 1], qf[kc], b2, b3);
                    }
                }
            }

            // ---- causal mask on raw scores (straddle tile only: j == ntile-1) ----
            bool needMask = (j * BN + BN - 1) > wrow;
            if (needMask) {
                int c0 = j * BN + (lane & 3) * 2;
                #pragma unroll
                for (int nt = 0; nt < 8; nt++) {
                    int cc = c0 + nt * 8;
                    if (cc     > r0g) sc[nt][0] = -1e30f;
                    if (cc + 1 > r0g) sc[nt][1] = -1e30f;
                    if (cc     > r1g) sc[nt][2] = -1e30f;
                    if (cc + 1 > r1g) sc[nt][3] = -1e30f;
                }
            }

            // ---- max on RAW scores; cross-quad reduce packed in fp16 (2 shfls) ----
            float t0 = sc[0][0], t1 = sc[0][2];
            #pragma unroll
            for (int nt = 0; nt < 8; nt++) {
                t0 = fmaxf(t0, fmaxf(sc[nt][0], sc[nt][1]));
                t1 = fmaxf(t1, fmaxf(sc[nt][2], sc[nt][3]));
            }
            // pack (t0,t1) -> half2, hmax2-reduce across the 4 lanes of the quad.
            // fp16 max granularity only loosens the exp-range guard; the common
            // factor 2^(-m) cancels between P and l in the final normalization.
            half2 hv = __floats2half2_rn(t0, t1);
            {
                uint32_t u = *reinterpret_cast<uint32_t*>(&hv);
                uint32_t v1 = __shfl_xor_sync(0xffffffffu, u, 1);
                hv = __hmax2(hv, *reinterpret_cast<half2*>(&v1));
                u = *reinterpret_cast<uint32_t*>(&hv);
                uint32_t v2 = __shfl_xor_sync(0xffffffffu, u, 2);
                hv = __hmax2(hv, *reinterpret_cast<half2*>(&v2));
            }
            float nm0 = fmaxf(m0, __low2float(hv)  * SL);
            float nm1 = fmaxf(m1, __high2float(hv) * SL);
            float a0 = exp2f(m0 - nm0), a1 = exp2f(m1 - nm1);
            m0 = nm0; m1 = nm1;

            // ---- h = s*SL - m ----
            #pragma unroll
            for (int nt = 0; nt < 8; nt++) {
                sc[nt][0] = fmaf(sc[nt][0], SL, -m0);
                sc[nt][1] = fmaf(sc[nt][1], SL, -m0);
                sc[nt][2] = fmaf(sc[nt][2], SL, -m1);
                sc[nt][3] = fmaf(sc[nt][3], SL, -m1);
            }

            // ---- rescale O and l only when a row max moved (exact skip of x1.0) ----
            if (__any_sync(0xffffffffu, (a0 != 1.f) || (a1 != 1.f))) {
                #pragma unroll
                for (int t = 0; t < 16; t++) {
                    ot[t][0] *= a0; ot[t][1] *= a0;
                    ot[t][2] *= a1; ot[t][3] *= a1;
                }
                lacc[0] *= a0; lacc[2] *= a1;
            }

            // ---- P = ex2(h) fp16x2; PV mma + l via ones-column mma ----
            {
                int jj = lane >> 3, mm = lane & 7;
                int rk = (jj & 1) * 8 + mm;
                int cn = (jj >= 2) ? 8 : 0;
                #pragma unroll
                for (int kvc = 0; kvc < 4; kvc++) {
                    uint32_t af[4];
                    af[0] = exp2_h2(sc[2 * kvc][0],     sc[2 * kvc][1]);
                    af[1] = exp2_h2(sc[2 * kvc][2],     sc[2 * kvc][3]);
                    af[2] = exp2_h2(sc[2 * kvc + 1][0], sc[2 * kvc + 1][1]);
                    af[3] = exp2_h2(sc[2 * kvc + 1][2], sc[2 * kvc + 1][3]);
                    mma16816(lacc, af, onesB, onesB);
                    #pragma unroll
                    for (int dp = 0; dp < 8; dp++) {
                        uint32_t b0, b1, b2, b3;
                        uint32_t a = smem_u32(sV + (kvc * 16 + rk) * STRIDE + dp * 16 + cn);
                        ldm_x4_t(b0, b1, b2, b3, a);
                        mma16816(ot[2 * dp],     af, b0, b1);
                        mma16816(ot[2 * dp + 1], af, b2, b3);
                    }
                }
            }
        }

        __syncthreads();
        if (j + 2 < ntile) load_kv(j + 2, j & 1);
        asm volatile("cp.async.commit_group;\n");
    }

    // ---- epilogue: broadcast l (col 0 lives in lane&~3), normalize, store ----
    float lr0 = __shfl_sync(0xffffffffu, lacc[0], lane & ~3);
    float lr1 = __shfl_sync(0xffffffffu, lacc[2], lane & ~3);
    float inv0 = 1.f / lr0, inv1 = 1.f / lr1;
    float* og = o + tok0 * QSTR + (size_t)hq * D_;
    int rr0 = warp * 16 + (lane >> 2);
    #pragma unroll
    for (int nt = 0; nt < 16; nt++) {
        int c = nt * 8 + (lane & 3) * 2;
        float2 w0 = make_float2(ot[nt][0] * inv0, ot[nt][1] * inv0);
        float2 w1 = make_float2(ot[nt][2] * inv1, ot[nt][3] * inv1);
        *(float2*)(og + (size_t)rr0 * QSTR + c)       = w0;
        *(float2*)(og + (size_t)(rr0 + 8) * QSTR + c) = w1;
    }
}

extern "C" void kernel_launch(void* const* d_in, const int* in_sizes, int n_in,
                              void* d_out, int out_size)
{
    const float* q = (const float*)d_in[0];
    const float* k = (const float*)d_in[1];
    const float* v = (const float*)d_in[2];
    float* o = (float*)d_out;

    cvt_kernel<<<2048, 256>>>(k, v);

    cudaFuncSetAttribute(fa2_kernel, cudaFuncAttributeMaxDynamicSharedMemorySize, SMEM_BYTES);
    dim3 grid(S_ / BM, H_, 2);   // 32 x 32 x 2 = 2048 CTAs
    fa2_kernel<<<grid, NT, SMEM_BYTES>>>(q, o);
}

// round 17
// speedup vs baseline: 1.5052x; 1.0337x over previous
#include <cuda_runtime.h>
#include <cuda_fp16.h>
#include <cstdint>

namespace {
constexpr int S_    = 2048;
constexpr int H_    = 32;
constexpr int G_    = 4;
constexpr int D_    = 128;
constexpr int QSTR  = 4096;   // H*D floats per token (q, out)
constexpr int KSTR  = 1024;   // HKV*D per token (k, v)
constexpr int BM    = 64;     // q rows per CTA
constexpr int BN    = 64;     // kv rows per tile
constexpr int NT    = 128;    // threads (4 warps)
constexpr int STRIDE = 136;   // smem row stride in halves (128 + 8 pad)
constexpr int KV_ELE = BN * STRIDE;
// sQ (64 rows) + 2*sK + 2*sV
constexpr int SMEM_BYTES = (BM * STRIDE + 4 * KV_ELE) * 2;   // 87,040 B -> 2 CTAs/SM
constexpr float SL = 0.08838834764831845f * 1.4426950408889634f;  // SCALE*log2(e)
}

// fp16 copies of K/V (scratch)
__device__ __align__(16) half g_kh[2 * S_ * KSTR];
__device__ __align__(16) half g_vh[2 * S_ * KSTR];

__device__ __forceinline__ uint32_t smem_u32(const void* p) {
    return (uint32_t)__cvta_generic_to_shared(p);
}
__device__ __forceinline__ void cp_async16(uint32_t dst, const void* src) {
    asm volatile("cp.async.cg.shared.global [%0], [%1], 16;\n" :: "r"(dst), "l"(src));
}
__device__ __forceinline__ void ldm_x4(uint32_t& r0, uint32_t& r1, uint32_t& r2, uint32_t& r3, uint32_t a) {
    asm volatile("ldmatrix.sync.aligned.m8n8.x4.shared.b16 {%0,%1,%2,%3}, [%4];\n"
        : "=r"(r0), "=r"(r1), "=r"(r2), "=r"(r3) : "r"(a));
}
__device__ __forceinline__ void ldm_x4_t(uint32_t& r0, uint32_t& r1, uint32_t& r2, uint32_t& r3, uint32_t a) {
    asm volatile("ldmatrix.sync.aligned.m8n8.x4.trans.shared.b16 {%0,%1,%2,%3}, [%4];\n"
        : "=r"(r0), "=r"(r1), "=r"(r2), "=r"(r3) : "r"(a));
}
// f32-accum mma (PV and l)
__device__ __forceinline__ void mma16816(float* c, const uint32_t* a, uint32_t b0, uint32_t b1) {
    asm volatile("mma.sync.aligned.m16n8k16.row.col.f32.f16.f16.f32 "
        "{%0,%1,%2,%3}, {%4,%5,%6,%7}, {%8,%9}, {%0,%1,%2,%3};\n"
        : "+f"(c[0]), "+f"(c[1]), "+f"(c[2]), "+f"(c[3])
        : "r"(a[0]), "r"(a[1]), "r"(a[2]), "r"(a[3]), "r"(b0), "r"(b1));
}
// f16-accum mma (S = QK^T): d0 = packed {c0,c1} of row r, d1 = packed {c2,c3} of row r+8
__device__ __forceinline__ void mma16816h(uint32_t& d0, uint32_t& d1, const uint32_t* a,
                                          uint32_t b0, uint32_t b1) {
    asm volatile("mma.sync.aligned.m16n8k16.row.col.f16.f16.f16.f16 "
        "{%0,%1}, {%2,%3,%4,%5}, {%6,%7}, {%0,%1};\n"
        : "+r"(d0), "+r"(d1)
        : "r"(a[0]), "r"(a[1]), "r"(a[2]), "r"(a[3]), "r"(b0), "r"(b1));
}
__device__ __forceinline__ uint32_t packh2(float x, float y) {
    half2 h = __floats2half2_rn(x, y);
    return *reinterpret_cast<uint32_t*>(&h);
}
__device__ __forceinline__ uint32_t ex2h2(uint32_t h) {
    uint32_t p;
    asm volatile("ex2.approx.f16x2 %0, %1;\n" : "=r"(p) : "r"(h));
    return p;
}
__device__ __forceinline__ half2 u2h(uint32_t u) { return *reinterpret_cast<half2*>(&u); }
__device__ __forceinline__ uint32_t h2u(half2 h) { return *reinterpret_cast<uint32_t*>(&h); }

// ---- K/V fp32 -> fp16 convert pass ----
__global__ void cvt_kernel(const float* __restrict__ k, const float* __restrict__ v) {
    const size_t n4 = (size_t)2 * S_ * KSTR / 4;
    for (size_t i = (size_t)blockIdx.x * blockDim.x + threadIdx.x;
         i < 2 * n4; i += (size_t)gridDim.x * blockDim.x) {
        bool isK = i < n4;
        size_t ii = isK ? i : i - n4;
        float4 f = isK ? ((const float4*)k)[ii] : ((const float4*)v)[ii];
        uint2 h;
        h.x = packh2(f.x, f.y);
        h.y = packh2(f.z, f.w);
        ((uint2*)(isK ? g_kh : g_vh))[ii] = h;
    }
}

__global__ __launch_bounds__(NT, 2)
void fa2_kernel(const float* __restrict__ q, float* __restrict__ o)
{
    extern __shared__ __align__(16) half smem[];
    half* sQ    = smem;                     // BM * STRIDE
    half* sKbuf = smem + BM * STRIDE;       // 2 bufs
    half* sVbuf = sKbuf + 2 * KV_ELE;       // 2 bufs

    const int tid  = threadIdx.x;
    const int warp = tid >> 5;
    const int lane = tid & 31;
    const int qt   = (int)gridDim.x - 1 - (int)blockIdx.x;  // heavy tiles first
    const int hq   = blockIdx.y;
    const int b    = blockIdx.z;
    const int hkv  = hq / G_;
    const int qbase = qt * BM;
    const int ntile = (qbase + BM) / BN;   // = qt + 1 >= 1

    const size_t tok0 = (size_t)b * S_ + qbase;
    const half* kg = g_kh + ((size_t)b * S_) * KSTR + (size_t)hkv * D_;
    const half* vg = g_vh + ((size_t)b * S_) * KSTR + (size_t)hkv * D_;

    auto load_kv = [&](int j, int buf) {
        const half* kt = kg + (size_t)(j * BN) * KSTR;
        const half* vt = vg + (size_t)(j * BN) * KSTR;
        half* dK = sKbuf + buf * KV_ELE;
        half* dV = sVbuf + buf * KV_ELE;
        #pragma unroll
        for (int i = tid; i < BN * 16; i += NT) {
            int r = i >> 4, c = (i & 15) * 8;
            cp_async16(smem_u32(dK + r * STRIDE + c), kt + (size_t)r * KSTR + c);
            cp_async16(smem_u32(dV + r * STRIDE + c), vt + (size_t)r * KSTR + c);
        }
    };
    load_kv(0, 0);
    asm volatile("cp.async.commit_group;\n");
    if (1 < ntile) load_kv(1, 1);
    asm volatile("cp.async.commit_group;\n");

    // ---- stage Q scaled by SL (fp32 -> fp16) while cp.async is in flight ----
    // Scores then emerge from the S-mma already in the exp2 domain.
    const float* qg = q + tok0 * QSTR + (size_t)hq * D_;
    for (int i = tid; i < BM * 32; i += NT) {
        int r = i >> 5, c = (i & 31) * 4;
        float4 f = *(const float4*)(qg + (size_t)r * QSTR + c);
        half2* d = (half2*)(sQ + r * STRIDE + c);
        d[0] = __floats2half2_rn(f.x * SL, f.y * SL);
        d[1] = __floats2half2_rn(f.z * SL, f.w * SL);
    }
    __syncthreads();

    // ---- Q fragments (persistent); warp owns rows warp*16 .. +15 ----
    uint32_t qf[8][4];
    {
        int j = lane >> 3, m = lane & 7;
        int row = warp * 16 + ((j & 1) ? 8 : 0) + m;
        int col = (j >= 2) ? 8 : 0;
        #pragma unroll
        for (int kc = 0; kc < 8; kc++) {
            uint32_t a = smem_u32(sQ + row * STRIDE + kc * 16 + col);
            ldm_x4(qf[kc][0], qf[kc][1], qf[kc][2], qf[kc][3], a);
        }
    }

    float ot[16][4];
    #pragma unroll
    for (int t = 0; t < 16; t++)
        #pragma unroll
        for (int i = 0; i < 4; i++) ot[t][i] = 0.f;
    float lacc[4] = {0.f, 0.f, 0.f, 0.f};  // l via ones-column mma (fp32 accum)
    float m0 = -1e30f, m1 = -1e30f;

    const uint32_t onesB = (lane < 4) ? 0x3C003C00u : 0u;

    const int r0g = qbase + warp * 16 + (lane >> 2);
    const int r1g = r0g + 8;
    const int wrow = qbase + warp * 16;

    for (int j = 0; j < ntile; j++) {
        asm volatile("cp.async.wait_group 1;\n");
        __syncthreads();

        const half* sK = sKbuf + (j & 1) * KV_ELE;
        const half* sV = sVbuf + (j & 1) * KV_ELE;

        {
            // ---- S = Q K^T, fp16 accumulate (scores pre-scaled via Q) ----
            // sdl[nt] = packed scores (c,c+1) of row r; sdh[nt] = row r+8.
            uint32_t sdl[8], sdh[8];
            #pragma unroll
            for (int t = 0; t < 8; t++) { sdl[t] = 0u; sdh[t] = 0u; }
            {
                int jj = lane >> 3, mm = lane & 7;
                int rn = ((jj >= 2) ? 8 : 0) + mm;
                int ck = (jj & 1) ? 8 : 0;
                #pragma unroll
                for (int kc = 0; kc < 8; kc++) {
                    #pragma unroll
                    for (int np = 0; np < 4; np++) {
                        uint32_t a = smem_u32(sK + (np * 16 + rn) * STRIDE + kc * 16 + ck);
                        uint32_t b0, b1, b2, b3;
                        ldm_x4(b0, b1, b2, b3, a);
                        mma16816h(sdl[2 * np],     sdh[2 * np],     qf[kc], b0, b1);
                        mma16816h(sdl[2 * np + 1], sdh[2 * np + 1], qf[kc], b2, b3);
                    }
                }
            }

            // ---- packed max (masked-out scores may contribute: they are bounded
            // real dot products; an elevated m is a common factor that cancels) ----
            half2 mxl = u2h(sdl[0]), mxh = u2h(sdh[0]);
            #pragma unroll
            for (int t = 1; t < 8; t++) {
                mxl = __hmax2(mxl, u2h(sdl[t]));
                mxh = __hmax2(mxh, u2h(sdh[t]));
            }
            half2 hv = __halves2half2(
                __hmax(__low2half(mxl), __high2half(mxl)),
                __hmax(__low2half(mxh), __high2half(mxh)));
            {
                uint32_t u = h2u(hv);
                uint32_t v1 = __shfl_xor_sync(0xffffffffu, u, 1);
                hv = __hmax2(hv, u2h(v1));
                u = h2u(hv);
                uint32_t v2 = __shfl_xor_sync(0xffffffffu, u, 2);
                hv = __hmax2(hv, u2h(v2));
            }
            float nm0 = fmaxf(m0, __low2float(hv));
            float nm1 = fmaxf(m1, __high2float(hv));
            float a0 = exp2f(m0 - nm0), a1 = exp2f(m1 - nm1);
            m0 = nm0; m1 = nm1;

            // ---- p = ex2(s - m), all packed fp16 ----
            half2 m02 = __float2half2_rn(m0);
            half2 m12 = __float2half2_rn(m1);
            #pragma unroll
            for (int t = 0; t < 8; t++) {
                sdl[t] = ex2h2(h2u(__hsub2(u2h(sdl[t]), m02)));
                sdh[t] = ex2h2(h2u(__hsub2(u2h(sdh[t]), m12)));
            }

            // ---- causal mask: zero P for future keys (straddle tile only) ----
            bool needMask = (j * BN + BN - 1) > wrow;
            if (needMask) {
                int c0 = j * BN + (lane & 3) * 2;
                #pragma unroll
                for (int t = 0; t < 8; t++) {
                    int cc = c0 + t * 8;
                    uint32_t kl = (cc <= r0g ? 0x3C00u : 0u) | (cc + 1 <= r0g ? 0x3C000000u : 0u);
                    uint32_t kh = (cc <= r1g ? 0x3C00u : 0u) | (cc + 1 <= r1g ? 0x3C000000u : 0u);
                    sdl[t] = h2u(__hmul2(u2h(sdl[t]), u2h(kl)));
                    sdh[t] = h2u(__hmul2(u2h(sdh[t]), u2h(kh)));
                }
            }

            // ---- rescale O and l ----
            #pragma unroll
            for (int t = 0; t < 16; t++) {
                ot[t][0] *= a0; ot[t][1] *= a0;
                ot[t][2] *= a1; ot[t][3] *= a1;
            }
            lacc[0] *= a0; lacc[2] *= a1;

            // ---- PV mma + l via ones-column mma (P fragments = sdl/sdh directly) ----
            {
                int jj = lane >> 3, mm = lane & 7;
                int rk = (jj & 1) * 8 + mm;
                int cn = (jj >= 2) ? 8 : 0;
                #pragma unroll
                for (int kvc = 0; kvc < 4; kvc++) {
                    uint32_t af[4];
                    af[0] = sdl[2 * kvc];
                    af[1] = sdh[2 * kvc];
                    af[2] = sdl[2 * kvc + 1];
                    af[3] = sdh[2 * kvc + 1];
                    mma16816(lacc, af, onesB, onesB);
                    #pragma unroll
                    for (int dp = 0; dp < 8; dp++) {
                        uint32_t b0, b1, b2, b3;
                        uint32_t a = smem_u32(sV + (kvc * 16 + rk) * STRIDE + dp * 16 + cn);
                        ldm_x4_t(b0, b1, b2, b3, a);
                        mma16816(ot[2 * dp],     af, b0, b1);
                        mma16816(ot[2 * dp + 1], af, b2, b3);
                    }
                }
            }
        }

        __syncthreads();
        if (j + 2 < ntile) load_kv(j + 2, j & 1);
        asm volatile("cp.async.commit_group;\n");
    }

    // ---- epilogue: broadcast l (col 0 lives in lane&~3), normalize, store ----
    float lr0 = __shfl_sync(0xffffffffu, lacc[0], lane & ~3);
    float lr1 = __shfl_sync(0xffffffffu, lacc[2], lane & ~3);
    float inv0 = 1.f / lr0, inv1 = 1.f / lr1;
    float* og = o + tok0 * QSTR + (size_t)hq * D_;
    int rr0 = warp * 16 + (lane >> 2);
    #pragma unroll
    for (int nt = 0; nt < 16; nt++) {
        int c = nt * 8 + (lane & 3) * 2;
        float2 w0 = make_float2(ot[nt][0] * inv0, ot[nt][1] * inv0);
        float2 w1 = make_float2(ot[nt][2] * inv1, ot[nt][3] * inv1);
        *(float2*)(og + (size_t)rr0 * QSTR + c)       = w0;
        *(float2*)(og + (size_t)(rr0 + 8) * QSTR + c) = w1;
    }
}

extern "C" void kernel_launch(void* const* d_in, const int* in_sizes, int n_in,
                              void* d_out, int out_size)
{
    const float* q = (const float*)d_in[0];
    const float* k = (const float*)d_in[1];
    const float* v = (const float*)d_in[2];
    float* o = (float*)d_out;

    cvt_kernel<<<2048, 256>>>(k, v);

    cudaFuncSetAttribute(fa2_kernel, cudaFuncAttributeMaxDynamicSharedMemorySize, SMEM_BYTES);
    dim3 grid(S_ / BM, H_, 2);   // 32 x 32 x 2 = 2048 CTAs
    fa2_kernel<<<grid, NT, SMEM_BYTES>>>(q, o);
}